// round 2
// baseline (speedup 1.0000x reference)
#include <cuda_runtime.h>

// Problem constants
#define SS   2048
#define BBATCH 4
#define DDIM 1024
#define HH   16
#define DK   64
#define MM   (SS * BBATCH)   // 8192 rows for all GEMMs

__device__ __constant__ float kScale = 0.125f;  // 1/sqrt(64)

// Scratch (allocation-free rule: device globals)
__device__ float g_Qp[(size_t)BBATCH * HH * SS * DK];  // [B,H,S,DK]
__device__ float g_Kp[(size_t)BBATCH * HH * SS * DK];
__device__ float g_Vp[(size_t)BBATCH * HH * SS * DK];
__device__ float g_Xr[(size_t)MM * DDIM];              // [S*B, D] attention output

// ---------------------------------------------------------------------------
// Tiled fp32 GEMM: C = A @ W^T + bias
//   A: [8192, 1024] row-major, W: [1024(out), 1024(in)] row-major.
//   out_sel 0/1/2: scatter into g_Qp/g_Kp/g_Vp as [B,H,S,DK]
//   out_sel 3    : direct row-major write to out_ext ([S,B,D] flat)
//   A_ext == nullptr -> read A from g_Xr
// Tile: BM=64, BN=64, BK=16, 256 threads, 4x4 per thread.
// ---------------------------------------------------------------------------
__global__ void __launch_bounds__(256) gemm_kernel(
    const float* __restrict__ A_ext,
    const float* __restrict__ W,
    const float* __restrict__ bias,
    float* __restrict__ out_ext,
    int out_sel)
{
    __shared__ float Asm[16][68];
    __shared__ float Wsm[16][68];

    const float* A = A_ext ? A_ext : (const float*)g_Xr;

    const int tid = threadIdx.x;
    const int tx = tid & 15;          // 0..15 -> output cols tx*4..+3
    const int ty = tid >> 4;          // 0..15 -> output rows ty*4..+3
    const int m0 = blockIdx.y * 64;
    const int n0 = blockIdx.x * 64;

    const int lr = tid >> 2;          // 0..63 row within tile for loading
    const int lk = (tid & 3) * 4;     // k offset {0,4,8,12}

    const float* Aptr = A + (size_t)(m0 + lr) * DDIM + lk;
    const float* Wptr = W + (size_t)(n0 + lr) * DDIM + lk;

    float acc[4][4];
#pragma unroll
    for (int i = 0; i < 4; i++)
#pragma unroll
        for (int j = 0; j < 4; j++) acc[i][j] = 0.f;

    for (int k0 = 0; k0 < DDIM; k0 += 16) {
        float4 av = *(const float4*)(Aptr + k0);
        float4 wv = *(const float4*)(Wptr + k0);
        __syncthreads();
        Asm[lk + 0][lr] = av.x; Asm[lk + 1][lr] = av.y;
        Asm[lk + 2][lr] = av.z; Asm[lk + 3][lr] = av.w;
        Wsm[lk + 0][lr] = wv.x; Wsm[lk + 1][lr] = wv.y;
        Wsm[lk + 2][lr] = wv.z; Wsm[lk + 3][lr] = wv.w;
        __syncthreads();

#pragma unroll
        for (int k = 0; k < 16; k++) {
            float4 a = *(const float4*)&Asm[k][ty * 4];
            float4 w = *(const float4*)&Wsm[k][tx * 4];
            acc[0][0] += a.x * w.x; acc[0][1] += a.x * w.y; acc[0][2] += a.x * w.z; acc[0][3] += a.x * w.w;
            acc[1][0] += a.y * w.x; acc[1][1] += a.y * w.y; acc[1][2] += a.y * w.z; acc[1][3] += a.y * w.w;
            acc[2][0] += a.z * w.x; acc[2][1] += a.z * w.y; acc[2][2] += a.z * w.z; acc[2][3] += a.z * w.w;
            acc[3][0] += a.w * w.x; acc[3][1] += a.w * w.y; acc[3][2] += a.w * w.z; acc[3][3] += a.w * w.w;
        }
    }

    float* scat = (out_sel == 0) ? g_Qp : (out_sel == 1) ? g_Kp : g_Vp;

#pragma unroll
    for (int i = 0; i < 4; i++) {
        const int mg = m0 + ty * 4 + i;
#pragma unroll
        for (int j = 0; j < 4; j++) {
            const int ng = n0 + tx * 4 + j;
            const float v = acc[i][j] + bias[ng];
            if (out_sel < 3) {
                // m = s*B + b ; n = h*DK + dk  ->  [B,H,S,DK]
                const int s_ = mg >> 2;
                const int b_ = mg & 3;
                const int h_ = ng >> 6;
                const int dk = ng & 63;
                scat[(((size_t)(b_ * HH + h_)) * SS + s_) * DK + dk] = v;
            } else {
                out_ext[(size_t)mg * DDIM + ng] = v;
            }
        }
    }
}

// ---------------------------------------------------------------------------
// Causal flash attention, fp32.
// Grid: (64 bh, 16 qblocks). 128 threads; thread t owns query row qb*128+t.
// K/V streamed in 64-row tiles through smem (contiguous in [B,H,S,DK]).
// Output written directly to g_Xr[(s*B+b)*D + h*64 + dk].
// ---------------------------------------------------------------------------
__global__ void __launch_bounds__(128, 2) attn_kernel()
{
    __shared__ float4 Ksm[64 * 16];   // 64 keys x 64 floats
    __shared__ float4 Vsm[64 * 16];

    const int bh  = blockIdx.x;       // b*H + h
    const int qb  = blockIdx.y;       // 0..15
    const int tid = threadIdx.x;      // 0..127
    const int rg  = qb * 128 + tid;   // global query position

    const float* Qb = g_Qp + (size_t)bh * SS * DK;
    const float* Kb = g_Kp + (size_t)bh * SS * DK;
    const float* Vb = g_Vp + (size_t)bh * SS * DK;

    float4 q[16];
    {
        const float4* qsrc = (const float4*)(Qb + (size_t)rg * DK);
#pragma unroll
        for (int i = 0; i < 16; i++) q[i] = qsrc[i];
    }

    float4 acc[16];
#pragma unroll
    for (int i = 0; i < 16; i++) acc[i] = make_float4(0.f, 0.f, 0.f, 0.f);
    float mrun = -1e30f, lrun = 0.f;

    const int ktmax = 2 * qb + 1;     // causal: kv tiles needed for this q block
    for (int kt = 0; kt <= ktmax; kt++) {
        const float4* ks = (const float4*)(Kb + (size_t)kt * 64 * DK);
        const float4* vs = (const float4*)(Vb + (size_t)kt * 64 * DK);
        __syncthreads();
#pragma unroll
        for (int i = 0; i < 8; i++) {
            Ksm[tid + i * 128] = ks[tid + i * 128];
            Vsm[tid + i * 128] = vs[tid + i * 128];
        }
        __syncthreads();

        const int kbase = kt * 64;
        float sarr[64];
        float tmax = -1e30f;
#pragma unroll
        for (int j = 0; j < 64; j++) {
            const float4* kr = &Ksm[j * 16];
            float sum = 0.f;
#pragma unroll
            for (int i = 0; i < 16; i++) {
                float4 kv = kr[i];
                sum += q[i].x * kv.x + q[i].y * kv.y + q[i].z * kv.z + q[i].w * kv.w;
            }
            const float sc = (kbase + j <= rg) ? sum * kScale : -1e30f;
            sarr[j] = sc;
            tmax = fmaxf(tmax, sc);
        }

        const float mnew = fmaxf(mrun, tmax);
        const float corr = __expf(mrun - mnew);
        lrun *= corr;
#pragma unroll
        for (int i = 0; i < 16; i++) {
            acc[i].x *= corr; acc[i].y *= corr; acc[i].z *= corr; acc[i].w *= corr;
        }

#pragma unroll
        for (int j = 0; j < 64; j++) {
            const float p = __expf(sarr[j] - mnew);
            lrun += p;
            const float4* vr = &Vsm[j * 16];
#pragma unroll
            for (int i = 0; i < 16; i++) {
                float4 vv = vr[i];
                acc[i].x += p * vv.x; acc[i].y += p * vv.y;
                acc[i].z += p * vv.z; acc[i].w += p * vv.w;
            }
        }
        mrun = mnew;
    }

    const float inv = 1.0f / lrun;
    const int b_ = bh >> 4;   // bh / H
    const int h_ = bh & 15;   // bh % H
    float4* orow = (float4*)(g_Xr + ((size_t)rg * BBATCH + b_) * DDIM + h_ * DK);
#pragma unroll
    for (int i = 0; i < 16; i++) {
        float4 v = acc[i];
        orow[i] = make_float4(v.x * inv, v.y * inv, v.z * inv, v.w * inv);
    }
}

// ---------------------------------------------------------------------------
// Launch: Q/K/V projections -> attention -> output projection.
// Inputs (metadata order): query, key, value, mask, Wq, bq, Wk, bk, Wv, bv, Wo, bo
// ---------------------------------------------------------------------------
extern "C" void kernel_launch(void* const* d_in, const int* in_sizes, int n_in,
                              void* d_out, int out_size)
{
    (void)in_sizes; (void)n_in; (void)out_size;
    const float* query = (const float*)d_in[0];
    const float* key   = (const float*)d_in[1];
    const float* value = (const float*)d_in[2];
    // d_in[3] = mask (causality computed analytically; unused)
    const float* Wq = (const float*)d_in[4];
    const float* bq = (const float*)d_in[5];
    const float* Wk = (const float*)d_in[6];
    const float* bk = (const float*)d_in[7];
    const float* Wv = (const float*)d_in[8];
    const float* bv = (const float*)d_in[9];
    const float* Wo = (const float*)d_in[10];
    const float* bo = (const float*)d_in[11];
    float* out = (float*)d_out;

    dim3 gGemm(DDIM / 64, MM / 64);   // (16, 128)
    gemm_kernel<<<gGemm, 256>>>(query, Wq, bq, nullptr, 0);
    gemm_kernel<<<gGemm, 256>>>(key,   Wk, bk, nullptr, 1);
    gemm_kernel<<<gGemm, 256>>>(value, Wv, bv, nullptr, 2);

    attn_kernel<<<dim3(BBATCH * HH, SS / 128), 128>>>();

    gemm_kernel<<<gGemm, 256>>>(nullptr, Wo, bo, out, 3);
}

// round 3
// speedup vs baseline: 1.7975x; 1.7975x over previous
#include <cuda_runtime.h>
#include <cstdint>

// Problem constants
#define SS     2048
#define BBATCH 4
#define DDIM   1024
#define HH     16
#define DK     64
#define MM     (SS * BBATCH)   // 8192 rows for all GEMMs

__device__ __constant__ float kScale = 0.125f;  // 1/sqrt(64)

// Scratch (allocation-free rule: device globals)
__device__ float g_Qp[(size_t)BBATCH * HH * SS * DK];  // [B,H,S,DK]
__device__ float g_Kp[(size_t)BBATCH * HH * SS * DK];
__device__ float g_Vp[(size_t)BBATCH * HH * SS * DK];
__device__ float g_Xr[(size_t)MM * DDIM];              // [S*B, D] attention output

// ---------------------------------------------------------------------------
// tf32 helpers
// ---------------------------------------------------------------------------
__device__ __forceinline__ uint32_t f2tf32(float f) {
    uint32_t u;
    asm("cvt.rna.tf32.f32 %0, %1;" : "=r"(u) : "f"(f));
    return u;
}

__device__ __forceinline__ void mma_tf32(
    float& d0, float& d1, float& d2, float& d3,
    uint32_t a0, uint32_t a1, uint32_t a2, uint32_t a3,
    uint32_t b0, uint32_t b1)
{
    asm volatile(
        "mma.sync.aligned.m16n8k8.row.col.f32.tf32.tf32.f32 "
        "{%0,%1,%2,%3}, {%4,%5,%6,%7}, {%8,%9}, {%0,%1,%2,%3};"
        : "+f"(d0), "+f"(d1), "+f"(d2), "+f"(d3)
        : "r"(a0), "r"(a1), "r"(a2), "r"(a3), "r"(b0), "r"(b1));
}

// ---------------------------------------------------------------------------
// tf32 tensor-core GEMM: C = A @ W^T + bias
//   A: [8192,1024] row-major, W: [1024(out),1024(in)] row-major.
//   Block tile 128(M) x 64(N), K-step 16, 256 threads = 8 warps (4m x 2n),
//   warp tile 32x32 via m16n8k8 (2 m-tiles x 4 n-tiles).
//   out_sel 0/1/2: scatter into g_Qp/g_Kp/g_Vp as [B,H,S,DK]
//   out_sel 3    : row-major write to out_ext; A from g_Xr when A_ext null.
// ---------------------------------------------------------------------------
#define GBM 128
#define GBN 64
#define APAD 136   // 128+8  -> conflict-free a-frag LDS
#define WPAD 72    // 64+8   -> conflict-free b-frag LDS

__global__ void __launch_bounds__(256) gemm_tc_kernel(
    const float* __restrict__ A_ext,
    const float* __restrict__ W,
    const float* __restrict__ bias,
    float* __restrict__ out_ext,
    int out_sel)
{
    __shared__ uint32_t AsT[16][APAD];  // k-major: AsT[k][m]
    __shared__ uint32_t WsT[16][WPAD];  // k-major: WsT[k][n]

    const float* A = A_ext ? A_ext : (const float*)g_Xr;

    const int tid  = threadIdx.x;
    const int lane = tid & 31;
    const int warp = tid >> 5;
    const int wm   = warp & 3;          // 0..3 -> m offset wm*32
    const int wn   = warp >> 2;         // 0..1 -> n offset wn*32
    const int g    = lane >> 2;         // groupID 0..7
    const int t    = lane & 3;          // threadInGroup 0..3

    const int m0 = blockIdx.y * GBM;
    const int n0 = blockIdx.x * GBN;

    // G->S loader coordinates
    const int rowA0 = tid >> 1;               // wrong granularity fix below
    (void)rowA0;
    // A: 128 rows x 16 k = 512 float4; 2 per thread (idx = 2*tid, 2*tid+1)
    // W: 64 rows x 16 k = 256 float4; 1 per thread
    const int aIdx0 = tid * 2;
    const int wRow  = tid >> 2;
    const int wKq   = (tid & 3) * 4;

    float acc[2][4][4];
#pragma unroll
    for (int mt = 0; mt < 2; mt++)
#pragma unroll
        for (int nt = 0; nt < 4; nt++)
#pragma unroll
            for (int e = 0; e < 4; e++) acc[mt][nt][e] = 0.f;

    for (int k0 = 0; k0 < DDIM; k0 += 16) {
        // load to regs
        float4 av[2];
#pragma unroll
        for (int u = 0; u < 2; u++) {
            const int idx = aIdx0 + u;
            const int row = idx >> 2;
            const int kq  = (idx & 3) * 4;
            av[u] = *(const float4*)(A + (size_t)(m0 + row) * DDIM + k0 + kq);
        }
        float4 wv = *(const float4*)(W + (size_t)(n0 + wRow) * DDIM + k0 + wKq);

        __syncthreads();
#pragma unroll
        for (int u = 0; u < 2; u++) {
            const int idx = aIdx0 + u;
            const int row = idx >> 2;
            const int kq  = (idx & 3) * 4;
            AsT[kq + 0][row] = f2tf32(av[u].x);
            AsT[kq + 1][row] = f2tf32(av[u].y);
            AsT[kq + 2][row] = f2tf32(av[u].z);
            AsT[kq + 3][row] = f2tf32(av[u].w);
        }
        WsT[wKq + 0][wRow] = f2tf32(wv.x);
        WsT[wKq + 1][wRow] = f2tf32(wv.y);
        WsT[wKq + 2][wRow] = f2tf32(wv.z);
        WsT[wKq + 3][wRow] = f2tf32(wv.w);
        __syncthreads();

#pragma unroll
        for (int kk = 0; kk < 16; kk += 8) {
            uint32_t afr[2][4];
#pragma unroll
            for (int mt = 0; mt < 2; mt++) {
                const int r = wm * 32 + mt * 16 + g;
                afr[mt][0] = AsT[kk + t][r];
                afr[mt][1] = AsT[kk + t][r + 8];
                afr[mt][2] = AsT[kk + t + 4][r];
                afr[mt][3] = AsT[kk + t + 4][r + 8];
            }
            uint32_t bfr[4][2];
#pragma unroll
            for (int nt = 0; nt < 4; nt++) {
                const int c = wn * 32 + nt * 8 + g;
                bfr[nt][0] = WsT[kk + t][c];
                bfr[nt][1] = WsT[kk + t + 4][c];
            }
#pragma unroll
            for (int mt = 0; mt < 2; mt++)
#pragma unroll
                for (int nt = 0; nt < 4; nt++)
                    mma_tf32(acc[mt][nt][0], acc[mt][nt][1], acc[mt][nt][2], acc[mt][nt][3],
                             afr[mt][0], afr[mt][1], afr[mt][2], afr[mt][3],
                             bfr[nt][0], bfr[nt][1]);
        }
    }

    // Epilogue. c0,c1 = row g, cols 2t,2t+1 ; c2,c3 = row g+8.
    float* scat = (out_sel == 0) ? g_Qp : (out_sel == 1) ? g_Kp : g_Vp;

#pragma unroll
    for (int mt = 0; mt < 2; mt++) {
#pragma unroll
        for (int nt = 0; nt < 4; nt++) {
            const int cg = n0 + wn * 32 + nt * 8 + t * 2;
            const float b0 = bias[cg], b1 = bias[cg + 1];
#pragma unroll
            for (int half = 0; half < 2; half++) {
                const int rg_ = m0 + wm * 32 + mt * 16 + g + half * 8;
                const float v0 = acc[mt][nt][half * 2 + 0] + b0;
                const float v1 = acc[mt][nt][half * 2 + 1] + b1;
                if (out_sel < 3) {
                    // row = s*B + b ; col = h*64 + dk  ->  [B,H,S,DK]
                    const int s_ = rg_ >> 2;
                    const int b_ = rg_ & 3;
                    const int h_ = cg >> 6;
                    const int dk = cg & 63;   // even, dk+1 same head
                    *(float2*)&scat[(((size_t)(b_ * HH + h_)) * SS + s_) * DK + dk] =
                        make_float2(v0, v1);
                } else {
                    *(float2*)&out_ext[(size_t)rg_ * DDIM + cg] = make_float2(v0, v1);
                }
            }
        }
    }
}

// ---------------------------------------------------------------------------
// Causal flash attention, fp32, K/V tile = 32 rows (register-pressure fix).
// Grid: (64 bh, 16 qblocks). 128 threads; thread t owns query row qb*128+t.
// ---------------------------------------------------------------------------
__global__ void __launch_bounds__(128, 2) attn_kernel()
{
    __shared__ float4 Ksm[32 * 16];   // 32 keys x 64 floats
    __shared__ float4 Vsm[32 * 16];

    const int bh  = blockIdx.x;       // b*H + h
    const int qb  = blockIdx.y;       // 0..15
    const int tid = threadIdx.x;      // 0..127
    const int rg  = qb * 128 + tid;   // global query row
    const int rgw_max = qb * 128 + (tid & ~31) + 31;  // max row in this warp

    const float* Qb = g_Qp + (size_t)bh * SS * DK;
    const float* Kb = g_Kp + (size_t)bh * SS * DK;
    const float* Vb = g_Vp + (size_t)bh * SS * DK;

    float4 q[16];
    {
        const float4* qsrc = (const float4*)(Qb + (size_t)rg * DK);
#pragma unroll
        for (int i = 0; i < 16; i++) q[i] = qsrc[i];
    }

    float4 acc[16];
#pragma unroll
    for (int i = 0; i < 16; i++) acc[i] = make_float4(0.f, 0.f, 0.f, 0.f);
    float mrun = -1e30f, lrun = 0.f;

    const int ntiles = 4 * qb + 4;    // 32-key tiles covering causal extent
    for (int kt = 0; kt < ntiles; kt++) {
        const float4* ks = (const float4*)(Kb + (size_t)kt * 32 * DK);
        const float4* vs = (const float4*)(Vb + (size_t)kt * 32 * DK);
        __syncthreads();
#pragma unroll
        for (int i = 0; i < 4; i++) {
            Ksm[tid + i * 128] = ks[tid + i * 128];
            Vsm[tid + i * 128] = vs[tid + i * 128];
        }
        __syncthreads();

        const int kbase = kt * 32;
        if (kbase > rgw_max) continue;   // warp-uniform: fully masked tile

        float sarr[32];
        float tmax = -1e30f;
#pragma unroll
        for (int j = 0; j < 32; j++) {
            const float4* kr = &Ksm[j * 16];
            float sum = 0.f;
#pragma unroll
            for (int i = 0; i < 16; i++) {
                float4 kv = kr[i];
                sum += q[i].x * kv.x + q[i].y * kv.y + q[i].z * kv.z + q[i].w * kv.w;
            }
            const float sc = (kbase + j <= rg) ? sum * kScale : -1e30f;
            sarr[j] = sc;
            tmax = fmaxf(tmax, sc);
        }

        const float mnew = fmaxf(mrun, tmax);
        const float corr = __expf(mrun - mnew);
        lrun *= corr;
#pragma unroll
        for (int i = 0; i < 16; i++) {
            acc[i].x *= corr; acc[i].y *= corr; acc[i].z *= corr; acc[i].w *= corr;
        }

#pragma unroll
        for (int j = 0; j < 32; j++) {
            const float p = __expf(sarr[j] - mnew);
            lrun += p;
            const float4* vr = &Vsm[j * 16];
#pragma unroll
            for (int i = 0; i < 16; i++) {
                float4 vv = vr[i];
                acc[i].x += p * vv.x; acc[i].y += p * vv.y;
                acc[i].z += p * vv.z; acc[i].w += p * vv.w;
            }
        }
        mrun = mnew;
    }

    const float inv = 1.0f / lrun;
    const int b_ = bh >> 4;
    const int h_ = bh & 15;
    float4* orow = (float4*)(g_Xr + ((size_t)rg * BBATCH + b_) * DDIM + h_ * DK);
#pragma unroll
    for (int i = 0; i < 16; i++) {
        float4 v = acc[i];
        orow[i] = make_float4(v.x * inv, v.y * inv, v.z * inv, v.w * inv);
    }
}

// ---------------------------------------------------------------------------
// Launch: Q/K/V projections -> attention -> output projection.
// Inputs: query, key, value, mask, Wq, bq, Wk, bk, Wv, bv, Wo, bo
// ---------------------------------------------------------------------------
extern "C" void kernel_launch(void* const* d_in, const int* in_sizes, int n_in,
                              void* d_out, int out_size)
{
    (void)in_sizes; (void)n_in; (void)out_size;
    const float* query = (const float*)d_in[0];
    const float* key   = (const float*)d_in[1];
    const float* value = (const float*)d_in[2];
    const float* Wq = (const float*)d_in[4];
    const float* bq = (const float*)d_in[5];
    const float* Wk = (const float*)d_in[6];
    const float* bk = (const float*)d_in[7];
    const float* Wv = (const float*)d_in[8];
    const float* bv = (const float*)d_in[9];
    const float* Wo = (const float*)d_in[10];
    const float* bo = (const float*)d_in[11];
    float* out = (float*)d_out;

    dim3 gGemm(DDIM / GBN, MM / GBM);   // (16, 64)
    gemm_tc_kernel<<<gGemm, 256>>>(query, Wq, bq, nullptr, 0);
    gemm_tc_kernel<<<gGemm, 256>>>(key,   Wk, bk, nullptr, 1);
    gemm_tc_kernel<<<gGemm, 256>>>(value, Wv, bv, nullptr, 2);

    attn_kernel<<<dim3(BBATCH * HH, SS / 128), 128>>>();

    gemm_tc_kernel<<<gGemm, 256>>>(nullptr, Wo, bo, out, 3);
}

// round 4
// speedup vs baseline: 3.5330x; 1.9655x over previous
#include <cuda_runtime.h>
#include <cstdint>

// Problem constants
#define SS     2048
#define BBATCH 4
#define DDIM   1024
#define HH     16
#define DK     64
#define MM     (SS * BBATCH)

__device__ __constant__ float kScale = 0.125f;  // 1/sqrt(64)

// Scratch (allocation-free rule: device globals)
__device__ float g_Qp[(size_t)BBATCH * HH * SS * DK];  // [B,H,S,DK]
__device__ float g_Kp[(size_t)BBATCH * HH * SS * DK];
__device__ float g_Vp[(size_t)BBATCH * HH * SS * DK];
__device__ float g_Xr[(size_t)MM * DDIM];              // [S*B, D]

// ---------------------------------------------------------------------------
// tf32 helpers
// ---------------------------------------------------------------------------
__device__ __forceinline__ uint32_t f2tf32(float f) {
    uint32_t u;
    asm("cvt.rna.tf32.f32 %0, %1;" : "=r"(u) : "f"(f));
    return u;
}

__device__ __forceinline__ void mma_tf32(
    float& d0, float& d1, float& d2, float& d3,
    uint32_t a0, uint32_t a1, uint32_t a2, uint32_t a3,
    uint32_t b0, uint32_t b1)
{
    asm volatile(
        "mma.sync.aligned.m16n8k8.row.col.f32.tf32.tf32.f32 "
        "{%0,%1,%2,%3}, {%4,%5,%6,%7}, {%8,%9}, {%0,%1,%2,%3};"
        : "+f"(d0), "+f"(d1), "+f"(d2), "+f"(d3)
        : "r"(a0), "r"(a1), "r"(a2), "r"(a3), "r"(b0), "r"(b1));
}

// ---------------------------------------------------------------------------
// tf32 tensor-core GEMM: C = A @ W^T + bias, double-buffered smem.
//   Block tile 128(M) x 64(N), K-step 16, 256 threads = 8 warps (4m x 2n),
//   warp tile 32x32 via m16n8k8.
// ---------------------------------------------------------------------------
#define GBM 128
#define GBN 64
#define APAD 136
#define WPAD 72

__global__ void __launch_bounds__(256) gemm_tc_kernel(
    const float* __restrict__ A_ext,
    const float* __restrict__ W,
    const float* __restrict__ bias,
    float* __restrict__ out_ext,
    int out_sel)
{
    __shared__ uint32_t AsT[2][16][APAD];  // k-major: AsT[s][k][m]
    __shared__ uint32_t WsT[2][16][WPAD];  // k-major: WsT[s][k][n]

    const float* A = A_ext ? A_ext : (const float*)g_Xr;

    const int tid  = threadIdx.x;
    const int lane = tid & 31;
    const int warp = tid >> 5;
    const int wm   = warp & 3;
    const int wn   = warp >> 2;
    const int g    = lane >> 2;
    const int t    = lane & 3;

    const int m0 = blockIdx.y * GBM;
    const int n0 = blockIdx.x * GBN;

    // loader coords: A 128x16 = 512 float4, 2/thread; W 64x16 = 256 float4, 1/thread
    const int aRow0 = (tid * 2) >> 2;
    const int aKq0  = ((tid * 2) & 3) * 4;
    const int aRow1 = (tid * 2 + 1) >> 2;
    const int aKq1  = ((tid * 2 + 1) & 3) * 4;
    const int wRow  = tid >> 2;
    const int wKq   = (tid & 3) * 4;

    const float* Ap0 = A + (size_t)(m0 + aRow0) * DDIM + aKq0;
    const float* Ap1 = A + (size_t)(m0 + aRow1) * DDIM + aKq1;
    const float* Wp  = W + (size_t)(n0 + wRow) * DDIM + wKq;

    float acc[2][4][4];
#pragma unroll
    for (int mt = 0; mt < 2; mt++)
#pragma unroll
        for (int nt = 0; nt < 4; nt++)
#pragma unroll
            for (int e = 0; e < 4; e++) acc[mt][nt][e] = 0.f;

    float4 av0, av1, wv;
    // prologue: load k-tile 0
    av0 = *(const float4*)(Ap0);
    av1 = *(const float4*)(Ap1);
    wv  = *(const float4*)(Wp);
    {
        AsT[0][aKq0 + 0][aRow0] = f2tf32(av0.x); AsT[0][aKq0 + 1][aRow0] = f2tf32(av0.y);
        AsT[0][aKq0 + 2][aRow0] = f2tf32(av0.z); AsT[0][aKq0 + 3][aRow0] = f2tf32(av0.w);
        AsT[0][aKq1 + 0][aRow1] = f2tf32(av1.x); AsT[0][aKq1 + 1][aRow1] = f2tf32(av1.y);
        AsT[0][aKq1 + 2][aRow1] = f2tf32(av1.z); AsT[0][aKq1 + 3][aRow1] = f2tf32(av1.w);
        WsT[0][wKq + 0][wRow] = f2tf32(wv.x); WsT[0][wKq + 1][wRow] = f2tf32(wv.y);
        WsT[0][wKq + 2][wRow] = f2tf32(wv.z); WsT[0][wKq + 3][wRow] = f2tf32(wv.w);
    }
    __syncthreads();

    const int KT = DDIM / 16;  // 64
    for (int kt = 0; kt < KT; kt++) {
        if (kt + 1 < KT) {
            const int k0 = (kt + 1) * 16;
            av0 = *(const float4*)(Ap0 + k0);
            av1 = *(const float4*)(Ap1 + k0);
            wv  = *(const float4*)(Wp + k0);
        }
        const int s = kt & 1;
#pragma unroll
        for (int kk = 0; kk < 16; kk += 8) {
            uint32_t afr[2][4];
#pragma unroll
            for (int mt = 0; mt < 2; mt++) {
                const int r = wm * 32 + mt * 16 + g;
                afr[mt][0] = AsT[s][kk + t][r];
                afr[mt][1] = AsT[s][kk + t][r + 8];
                afr[mt][2] = AsT[s][kk + t + 4][r];
                afr[mt][3] = AsT[s][kk + t + 4][r + 8];
            }
            uint32_t bfr[4][2];
#pragma unroll
            for (int nt = 0; nt < 4; nt++) {
                const int c = wn * 32 + nt * 8 + g;
                bfr[nt][0] = WsT[s][kk + t][c];
                bfr[nt][1] = WsT[s][kk + t + 4][c];
            }
#pragma unroll
            for (int mt = 0; mt < 2; mt++)
#pragma unroll
                for (int nt = 0; nt < 4; nt++)
                    mma_tf32(acc[mt][nt][0], acc[mt][nt][1], acc[mt][nt][2], acc[mt][nt][3],
                             afr[mt][0], afr[mt][1], afr[mt][2], afr[mt][3],
                             bfr[nt][0], bfr[nt][1]);
        }
        if (kt + 1 < KT) {
            const int d = s ^ 1;
            AsT[d][aKq0 + 0][aRow0] = f2tf32(av0.x); AsT[d][aKq0 + 1][aRow0] = f2tf32(av0.y);
            AsT[d][aKq0 + 2][aRow0] = f2tf32(av0.z); AsT[d][aKq0 + 3][aRow0] = f2tf32(av0.w);
            AsT[d][aKq1 + 0][aRow1] = f2tf32(av1.x); AsT[d][aKq1 + 1][aRow1] = f2tf32(av1.y);
            AsT[d][aKq1 + 2][aRow1] = f2tf32(av1.z); AsT[d][aKq1 + 3][aRow1] = f2tf32(av1.w);
            WsT[d][wKq + 0][wRow] = f2tf32(wv.x); WsT[d][wKq + 1][wRow] = f2tf32(wv.y);
            WsT[d][wKq + 2][wRow] = f2tf32(wv.z); WsT[d][wKq + 3][wRow] = f2tf32(wv.w);
        }
        __syncthreads();
    }

    // Epilogue
    float* scat = (out_sel == 0) ? g_Qp : (out_sel == 1) ? g_Kp : g_Vp;

#pragma unroll
    for (int mt = 0; mt < 2; mt++) {
#pragma unroll
        for (int nt = 0; nt < 4; nt++) {
            const int cg = n0 + wn * 32 + nt * 8 + t * 2;
            const float b0 = bias[cg], b1 = bias[cg + 1];
#pragma unroll
            for (int half = 0; half < 2; half++) {
                const int rg_ = m0 + wm * 32 + mt * 16 + g + half * 8;
                const float v0 = acc[mt][nt][half * 2 + 0] + b0;
                const float v1 = acc[mt][nt][half * 2 + 1] + b1;
                if (out_sel < 3) {
                    const int s_ = rg_ >> 2;
                    const int b_ = rg_ & 3;
                    const int h_ = cg >> 6;
                    const int dk = cg & 63;
                    *(float2*)&scat[(((size_t)(b_ * HH + h_)) * SS + s_) * DK + dk] =
                        make_float2(v0, v1);
                } else {
                    *(float2*)&out_ext[(size_t)rg_ * DDIM + cg] = make_float2(v0, v1);
                }
            }
        }
    }
}

// ---------------------------------------------------------------------------
// Tensor-core causal flash attention (tf32).
// CTA: 128 q-rows, 8 warps x 16-row warp tiles. K/V tiles: 64 keys.
// Dynamic smem: K[64][68], V[64][68] (tf32), Q[128][68] (tf32, pre-scaled),
// P[128][68] (tf32, per-warp-private rows).
// ---------------------------------------------------------------------------
#define AT_PAD 68
#define AT_SMEM_BYTES ((2 * 64 * AT_PAD + 2 * 128 * AT_PAD) * 4)

__global__ void __launch_bounds__(256, 2) attn_tc_kernel()
{
    extern __shared__ uint32_t dsm[];
    uint32_t* Ksm = dsm;                    // [64][AT_PAD]
    uint32_t* Vsm = dsm + 64 * AT_PAD;      // [64][AT_PAD]
    uint32_t* Qsm = dsm + 2 * 64 * AT_PAD;  // [128][AT_PAD]
    uint32_t* Psm = Qsm + 128 * AT_PAD;     // [128][AT_PAD]

    const int bh   = blockIdx.x;            // b*H + h
    const int qb   = blockIdx.y;            // 0..15
    const int tid  = threadIdx.x;
    const int lane = tid & 31;
    const int warp = tid >> 5;              // 0..7
    const int g    = lane >> 2;
    const int t    = lane & 3;
    const int wrow = warp * 16;
    const int q0   = qb * 128;

    const float* Qb = g_Qp + (size_t)bh * SS * DK;
    const float* Kb = g_Kp + (size_t)bh * SS * DK;
    const float* Vb = g_Vp + (size_t)bh * SS * DK;

    // Stage Q (scaled, tf32) into Qsm: 128x16 float4, 8/thread, coalesced
#pragma unroll
    for (int i = 0; i < 8; i++) {
        const int idx = tid + i * 256;
        const int row = idx >> 4;
        const int c4  = (idx & 15) * 4;
        float4 v = *(const float4*)(Qb + (size_t)(q0 + row) * DK + c4);
        uint32_t* dst = Qsm + row * AT_PAD + c4;
        dst[0] = f2tf32(v.x * kScale);
        dst[1] = f2tf32(v.y * kScale);
        dst[2] = f2tf32(v.z * kScale);
        dst[3] = f2tf32(v.w * kScale);
    }
    // (first tile's post-load __syncthreads covers Q visibility)

    float oacc[8][4];
#pragma unroll
    for (int nt = 0; nt < 8; nt++)
#pragma unroll
        for (int e = 0; e < 4; e++) oacc[nt][e] = 0.f;

    float m_t = -1e30f, m_b = -1e30f, l_t = 0.f, l_b = 0.f;
    const int rtop = q0 + wrow + g;
    const int rbot = rtop + 8;
    const int wmax = q0 + wrow + 15;

    const int ntiles = 2 * qb + 2;
    for (int kt = 0; kt < ntiles; kt++) {
        const int kbase = kt * 64;
        __syncthreads();
#pragma unroll
        for (int i = 0; i < 4; i++) {
            const int idx = tid + i * 256;
            const int row = idx >> 4;
            const int c4  = (idx & 15) * 4;
            float4 kv = *(const float4*)(Kb + (size_t)(kbase + row) * DK + c4);
            float4 vv = *(const float4*)(Vb + (size_t)(kbase + row) * DK + c4);
            uint32_t* kd = Ksm + row * AT_PAD + c4;
            kd[0] = f2tf32(kv.x); kd[1] = f2tf32(kv.y);
            kd[2] = f2tf32(kv.z); kd[3] = f2tf32(kv.w);
            uint32_t* vd = Vsm + row * AT_PAD + c4;
            vd[0] = f2tf32(vv.x); vd[1] = f2tf32(vv.y);
            vd[2] = f2tf32(vv.z); vd[3] = f2tf32(vv.w);
        }
        __syncthreads();

        if (kbase > wmax) continue;   // warp fully masked for this tile

        // ---- S = Q @ K^T  (16 x 64) ----
        float sacc[8][4];
#pragma unroll
        for (int nt = 0; nt < 8; nt++)
#pragma unroll
            for (int e = 0; e < 4; e++) sacc[nt][e] = 0.f;

#pragma unroll
        for (int kk = 0; kk < 8; kk++) {
            const uint32_t* qr0 = Qsm + (wrow + g) * AT_PAD + kk * 8;
            const uint32_t* qr1 = Qsm + (wrow + g + 8) * AT_PAD + kk * 8;
            const uint32_t a0 = qr0[t], a1 = qr1[t];
            const uint32_t a2 = qr0[t + 4], a3 = qr1[t + 4];
#pragma unroll
            for (int nt = 0; nt < 8; nt++) {
                const uint32_t* kr = Ksm + (nt * 8 + g) * AT_PAD + kk * 8;
                mma_tf32(sacc[nt][0], sacc[nt][1], sacc[nt][2], sacc[nt][3],
                         a0, a1, a2, a3, kr[t], kr[t + 4]);
            }
        }

        // ---- causal mask (only near diagonal) ----
        if (kbase + 63 > q0 + wrow) {
#pragma unroll
            for (int nt = 0; nt < 8; nt++) {
                const int c0 = kbase + nt * 8 + 2 * t;
                if (c0 > rtop)     sacc[nt][0] = -1e30f;
                if (c0 + 1 > rtop) sacc[nt][1] = -1e30f;
                if (c0 > rbot)     sacc[nt][2] = -1e30f;
                if (c0 + 1 > rbot) sacc[nt][3] = -1e30f;
            }
        }

        // ---- online softmax ----
        float mx_t = -1e30f, mx_b = -1e30f;
#pragma unroll
        for (int nt = 0; nt < 8; nt++) {
            mx_t = fmaxf(mx_t, fmaxf(sacc[nt][0], sacc[nt][1]));
            mx_b = fmaxf(mx_b, fmaxf(sacc[nt][2], sacc[nt][3]));
        }
        mx_t = fmaxf(mx_t, __shfl_xor_sync(0xffffffffu, mx_t, 1));
        mx_t = fmaxf(mx_t, __shfl_xor_sync(0xffffffffu, mx_t, 2));
        mx_b = fmaxf(mx_b, __shfl_xor_sync(0xffffffffu, mx_b, 1));
        mx_b = fmaxf(mx_b, __shfl_xor_sync(0xffffffffu, mx_b, 2));

        const float mnew_t = fmaxf(m_t, mx_t);
        const float mnew_b = fmaxf(m_b, mx_b);
        const float corr_t = __expf(m_t - mnew_t);
        const float corr_b = __expf(m_b - mnew_b);
        m_t = mnew_t; m_b = mnew_b;

        float sum_t = 0.f, sum_b = 0.f;
#pragma unroll
        for (int nt = 0; nt < 8; nt++) {
            const float p0 = __expf(sacc[nt][0] - mnew_t);
            const float p1 = __expf(sacc[nt][1] - mnew_t);
            const float p2 = __expf(sacc[nt][2] - mnew_b);
            const float p3 = __expf(sacc[nt][3] - mnew_b);
            sum_t += p0 + p1;
            sum_b += p2 + p3;
            uint32_t* pr0 = Psm + (wrow + g) * AT_PAD + nt * 8 + 2 * t;
            uint32_t* pr1 = Psm + (wrow + g + 8) * AT_PAD + nt * 8 + 2 * t;
            pr0[0] = f2tf32(p0); pr0[1] = f2tf32(p1);
            pr1[0] = f2tf32(p2); pr1[1] = f2tf32(p3);
        }
        sum_t += __shfl_xor_sync(0xffffffffu, sum_t, 1);
        sum_t += __shfl_xor_sync(0xffffffffu, sum_t, 2);
        sum_b += __shfl_xor_sync(0xffffffffu, sum_b, 1);
        sum_b += __shfl_xor_sync(0xffffffffu, sum_b, 2);
        l_t = l_t * corr_t + sum_t;
        l_b = l_b * corr_b + sum_b;

#pragma unroll
        for (int nt = 0; nt < 8; nt++) {
            oacc[nt][0] *= corr_t; oacc[nt][1] *= corr_t;
            oacc[nt][2] *= corr_b; oacc[nt][3] *= corr_b;
        }

        __syncwarp();  // P writes visible to whole warp

        // ---- O += P @ V  (16 x 64 x 64) ----
#pragma unroll
        for (int kk = 0; kk < 8; kk++) {
            const uint32_t* pr0 = Psm + (wrow + g) * AT_PAD + kk * 8;
            const uint32_t* pr1 = Psm + (wrow + g + 8) * AT_PAD + kk * 8;
            const uint32_t a0 = pr0[t], a1 = pr1[t];
            const uint32_t a2 = pr0[t + 4], a3 = pr1[t + 4];
            const uint32_t* vr0 = Vsm + (kk * 8 + t) * AT_PAD;
            const uint32_t* vr1 = Vsm + (kk * 8 + t + 4) * AT_PAD;
#pragma unroll
            for (int nt = 0; nt < 8; nt++) {
                mma_tf32(oacc[nt][0], oacc[nt][1], oacc[nt][2], oacc[nt][3],
                         a0, a1, a2, a3, vr0[nt * 8 + g], vr1[nt * 8 + g]);
            }
        }
        __syncwarp();
    }

    // ---- epilogue: O / l, write to g_Xr[(s*B+b)*D + h*64 + dk] ----
    const float inv_t = 1.0f / l_t;
    const float inv_b = 1.0f / l_b;
    const int b_ = bh >> 4;
    const int h_ = bh & 15;
    float* o_t = g_Xr + ((size_t)rtop * BBATCH + b_) * DDIM + h_ * DK;
    float* o_b = g_Xr + ((size_t)rbot * BBATCH + b_) * DDIM + h_ * DK;
#pragma unroll
    for (int nt = 0; nt < 8; nt++) {
        const int c = nt * 8 + 2 * t;
        *(float2*)(o_t + c) = make_float2(oacc[nt][0] * inv_t, oacc[nt][1] * inv_t);
        *(float2*)(o_b + c) = make_float2(oacc[nt][2] * inv_b, oacc[nt][3] * inv_b);
    }
}

// ---------------------------------------------------------------------------
// Launch
// ---------------------------------------------------------------------------
extern "C" void kernel_launch(void* const* d_in, const int* in_sizes, int n_in,
                              void* d_out, int out_size)
{
    (void)in_sizes; (void)n_in; (void)out_size;
    const float* query = (const float*)d_in[0];
    const float* key   = (const float*)d_in[1];
    const float* value = (const float*)d_in[2];
    const float* Wq = (const float*)d_in[4];
    const float* bq = (const float*)d_in[5];
    const float* Wk = (const float*)d_in[6];
    const float* bk = (const float*)d_in[7];
    const float* Wv = (const float*)d_in[8];
    const float* bv = (const float*)d_in[9];
    const float* Wo = (const float*)d_in[10];
    const float* bo = (const float*)d_in[11];
    float* out = (float*)d_out;

    cudaFuncSetAttribute(attn_tc_kernel,
                         cudaFuncAttributeMaxDynamicSharedMemorySize, AT_SMEM_BYTES);

    dim3 gGemm(DDIM / GBN, MM / GBM);   // (16, 64)
    gemm_tc_kernel<<<gGemm, 256>>>(query, Wq, bq, nullptr, 0);
    gemm_tc_kernel<<<gGemm, 256>>>(key,   Wk, bk, nullptr, 1);
    gemm_tc_kernel<<<gGemm, 256>>>(value, Wv, bv, nullptr, 2);

    attn_tc_kernel<<<dim3(BBATCH * HH, 16), 256, AT_SMEM_BYTES>>>();

    gemm_tc_kernel<<<gGemm, 256>>>(nullptr, Wo, bo, out, 3);
}

// round 7
// speedup vs baseline: 4.2486x; 1.2025x over previous
#include <cuda_runtime.h>
#include <cstdint>

#define SS     2048
#define BBATCH 4
#define DDIM   1024
#define HH     16
#define DK     64
#define MM     (SS * BBATCH)
#define LOG2E  1.44269504f
#define QSCALE 0.125f

// ---------------- device scratch (tf32 bits in uint32) ----------------
__device__ uint32_t g_Aq[(size_t)MM * DDIM];
__device__ uint32_t g_Ak[(size_t)MM * DDIM];
__device__ uint32_t g_Av[(size_t)MM * DDIM];
__device__ uint32_t g_Wqt[(size_t)DDIM * DDIM];
__device__ uint32_t g_Wkt[(size_t)DDIM * DDIM];
__device__ uint32_t g_Wvt[(size_t)DDIM * DDIM];
__device__ uint32_t g_Wot[(size_t)DDIM * DDIM];
__device__ uint32_t g_Qp[(size_t)BBATCH * HH * SS * DK];  // [B,H,S,DK] tf32 (scaled)
__device__ uint32_t g_Kp[(size_t)BBATCH * HH * SS * DK];
__device__ uint32_t g_Vp[(size_t)BBATCH * HH * SS * DK];
__device__ uint32_t g_Xr[(size_t)MM * DDIM];              // attn out, tf32 bits

// ---------------- helpers ----------------
__device__ __forceinline__ uint32_t f2tf32(float f) {
    uint32_t u;
    asm("cvt.rna.tf32.f32 %0, %1;" : "=r"(u) : "f"(f));
    return u;
}
__device__ __forceinline__ float ex2(float x) {
    float y; asm("ex2.approx.f32 %0, %1;" : "=f"(y) : "f"(x)); return y;
}
__device__ __forceinline__ void mma_tf32(
    float& d0, float& d1, float& d2, float& d3,
    uint32_t a0, uint32_t a1, uint32_t a2, uint32_t a3,
    uint32_t b0, uint32_t b1)
{
    asm volatile(
        "mma.sync.aligned.m16n8k8.row.col.f32.tf32.tf32.f32 "
        "{%0,%1,%2,%3}, {%4,%5,%6,%7}, {%8,%9}, {%0,%1,%2,%3};"
        : "+f"(d0), "+f"(d1), "+f"(d2), "+f"(d3)
        : "r"(a0), "r"(a1), "r"(a2), "r"(a3), "r"(b0), "r"(b1));
}

// ---------------- pre-convert fp32 -> tf32 bits ----------------
__global__ void cvt_tf32_kernel(const float* __restrict__ src, int n4, int sel)
{
    uint32_t* dst = (sel == 0) ? g_Aq : (sel == 1) ? g_Ak : (sel == 2) ? g_Av :
                    (sel == 3) ? g_Wqt : (sel == 4) ? g_Wkt : (sel == 5) ? g_Wvt : g_Wot;
    int i = blockIdx.x * blockDim.x + threadIdx.x;
    if (i >= n4) return;
    float4 v = ((const float4*)src)[i];
    uint4 o;
    o.x = f2tf32(v.x); o.y = f2tf32(v.y); o.z = f2tf32(v.z); o.w = f2tf32(v.w);
    ((uint4*)dst)[i] = o;
}

// ---------------------------------------------------------------------------
// tf32 GEMM: C = A @ W^T + bias. Register-staged LDG->STS double buffer.
// Block tile 128x128, BK=16, 256 threads = 8 warps (2m x 4n), warp tile 64x32.
// smem row pad 20 words -> conflict-free frag LDS (20g mod 32 distinct).
// sel: 0/1/2 -> scatter tf32 into g_Qp(scaled)/g_Kp/g_Vp ; 3 -> fp32 out_ext.
// ---------------------------------------------------------------------------
#define GPAD 20

__global__ void __launch_bounds__(256) gemm_tc(
    const float* __restrict__ bias, float* __restrict__ out_ext, int sel)
{
    __shared__ uint32_t As[2][128 * GPAD];
    __shared__ uint32_t Ws[2][128 * GPAD];

    const uint32_t* A = (sel == 0) ? g_Aq : (sel == 1) ? g_Ak : (sel == 2) ? g_Av : g_Xr;
    const uint32_t* W = (sel == 0) ? g_Wqt : (sel == 1) ? g_Wkt : (sel == 2) ? g_Wvt : g_Wot;

    const int tid  = threadIdx.x;
    const int lane = tid & 31;
    const int warp = tid >> 5;
    const int wm   = warp & 1;          // m offset wm*64
    const int wn   = warp >> 1;         // n offset wn*32
    const int g    = lane >> 2;
    const int t    = lane & 3;
    const int m0 = blockIdx.y * 128;
    const int n0 = blockIdx.x * 128;

    // loader: 512 uint4 chunks per tile (A and W each); 2 per thread.
    const int rA0 = (tid * 2) >> 2,     qA0 = ((tid * 2) & 3) * 4;
    const int rA1 = (tid * 2 + 1) >> 2, qA1 = ((tid * 2 + 1) & 3) * 4;

    const uint32_t* Ap0 = A + (size_t)(m0 + rA0) * DDIM + qA0;
    const uint32_t* Ap1 = A + (size_t)(m0 + rA1) * DDIM + qA1;
    const uint32_t* Wp0 = W + (size_t)(n0 + rA0) * DDIM + qA0;
    const uint32_t* Wp1 = W + (size_t)(n0 + rA1) * DDIM + qA1;

    float acc[4][4][4];
#pragma unroll
    for (int mt = 0; mt < 4; mt++)
#pragma unroll
        for (int nt = 0; nt < 4; nt++)
#pragma unroll
            for (int e = 0; e < 4; e++) acc[mt][nt][e] = 0.f;

    uint4 a0, a1, w0, w1;
    a0 = *(const uint4*)Ap0; a1 = *(const uint4*)Ap1;
    w0 = *(const uint4*)Wp0; w1 = *(const uint4*)Wp1;

    const int KT = DDIM / 16;  // 64
    for (int kt = 0; kt < KT; kt++) {
        const int s = kt & 1;
        *(uint4*)&As[s][rA0 * GPAD + qA0] = a0;
        *(uint4*)&As[s][rA1 * GPAD + qA1] = a1;
        *(uint4*)&Ws[s][rA0 * GPAD + qA0] = w0;
        *(uint4*)&Ws[s][rA1 * GPAD + qA1] = w1;
        __syncthreads();
        if (kt + 1 < KT) {
            const int k0 = (kt + 1) * 16;
            a0 = *(const uint4*)(Ap0 + k0); a1 = *(const uint4*)(Ap1 + k0);
            w0 = *(const uint4*)(Wp0 + k0); w1 = *(const uint4*)(Wp1 + k0);
        }

        const uint32_t* as_ = As[s];
        const uint32_t* ws_ = Ws[s];
#pragma unroll
        for (int kk = 0; kk < 16; kk += 8) {
            uint32_t a[4][4];
#pragma unroll
            for (int mt = 0; mt < 4; mt++) {
                const uint32_t* p = as_ + (wm * 64 + mt * 16 + g) * GPAD + kk + t;
                a[mt][0] = p[0];
                a[mt][1] = p[8 * GPAD];
                a[mt][2] = p[4];
                a[mt][3] = p[8 * GPAD + 4];
            }
            uint32_t b[4][2];
#pragma unroll
            for (int nt = 0; nt < 4; nt++) {
                const uint32_t* p = ws_ + (wn * 32 + nt * 8 + g) * GPAD + kk + t;
                b[nt][0] = p[0];
                b[nt][1] = p[4];
            }
#pragma unroll
            for (int mt = 0; mt < 4; mt++)
#pragma unroll
                for (int nt = 0; nt < 4; nt++)
                    mma_tf32(acc[mt][nt][0], acc[mt][nt][1], acc[mt][nt][2], acc[mt][nt][3],
                             a[mt][0], a[mt][1], a[mt][2], a[mt][3],
                             b[nt][0], b[nt][1]);
        }
    }

    // epilogue
    uint32_t* scat = (sel == 0) ? g_Qp : (sel == 1) ? g_Kp : g_Vp;
#pragma unroll
    for (int mt = 0; mt < 4; mt++) {
#pragma unroll
        for (int nt = 0; nt < 4; nt++) {
            const int cg = n0 + wn * 32 + nt * 8 + 2 * t;
            const float b0 = bias[cg], b1 = bias[cg + 1];
#pragma unroll
            for (int half = 0; half < 2; half++) {
                const int rg_ = m0 + wm * 64 + mt * 16 + g + 8 * half;
                float v0 = acc[mt][nt][half * 2 + 0] + b0;
                float v1 = acc[mt][nt][half * 2 + 1] + b1;
                if (sel < 3) {
                    if (sel == 0) { v0 *= QSCALE; v1 *= QSCALE; }
                    const int s_ = rg_ >> 2, b_ = rg_ & 3;
                    const int h_ = cg >> 6,  dk = cg & 63;
                    uint2 o = make_uint2(f2tf32(v0), f2tf32(v1));
                    *(uint2*)&scat[(((size_t)(b_ * HH + h_)) * SS + s_) * DK + dk] = o;
                } else {
                    *(float2*)&out_ext[(size_t)rg_ * DDIM + cg] = make_float2(v0, v1);
                }
            }
        }
    }
}

// ---------------------------------------------------------------------------
// Tensor-core causal flash attention (tf32, operands pre-converted).
// CTA: 256 q-rows, 8 warps x 32-row warp tiles. K/V: 64-key tiles, 2-slot
// smem double buffer with register-staged prefetch.
// Pads: all rows 68 words (A/K frag conflict-free; V-frag & P-store 2-way).
// ---------------------------------------------------------------------------
#define AR    68
#define ASTG  (64 * AR)
#define AT_SMEM ((2 * 256 * AR + 4 * ASTG) * 4)   // (34816 + 17408)*4 = 208896 B

__global__ void __launch_bounds__(256, 1) attn_tc()
{
    extern __shared__ uint32_t dsm[];
    uint32_t* Qsm = dsm;                      // [256][AR]
    uint32_t* Psm = Qsm + 256 * AR;           // [256][AR]
    uint32_t* Ksm = Psm + 256 * AR;           // [2][64][AR]
    uint32_t* Vsm = Ksm + 2 * ASTG;           // [2][64][AR]

    const int bh   = blockIdx.x;
    const int qb   = (gridDim.y - 1) - blockIdx.y;   // heavy blocks first
    const int q0   = qb * 256;
    const int tid  = threadIdx.x;
    const int lane = tid & 31;
    const int warp = tid >> 5;
    const int g    = lane >> 2;
    const int t    = lane & 3;
    const int lr0  = warp * 32;

    const uint32_t* Qg = g_Qp + (size_t)bh * SS * DK + (size_t)q0 * DK;
    const uint32_t* Kg = g_Kp + (size_t)bh * SS * DK;
    const uint32_t* Vg = g_Vp + (size_t)bh * SS * DK;

    const int ntiles = 4 * qb + 4;

    // loader coords: K/V tile = 64 rows x 16 uint4 chunks = 1024 chunks, 4/thread
    int lrow[4], lq[4];
#pragma unroll
    for (int i = 0; i < 4; i++) {
        const int c = tid + i * 256;
        lrow[i] = c >> 4;
        lq[i]   = (c & 15) * 4;
    }

    // Stage Q into smem (visible after first loop barrier)
#pragma unroll
    for (int i = 0; i < 16; i++) {
        const int idx = tid + i * 256;
        const int row = idx >> 4;
        const int cq  = (idx & 15) * 4;
        *(uint4*)&Qsm[row * AR + cq] = *(const uint4*)(Qg + (size_t)row * DK + cq);
    }

    uint4 kst[4], vst[4];
#pragma unroll
    for (int i = 0; i < 4; i++) {
        kst[i] = *(const uint4*)(Kg + (size_t)lrow[i] * DK + lq[i]);
        vst[i] = *(const uint4*)(Vg + (size_t)lrow[i] * DK + lq[i]);
    }

    float m_[4], l_[4];
#pragma unroll
    for (int i = 0; i < 4; i++) { m_[i] = -1e30f; l_[i] = 0.f; }
    float oacc[2][8][4];
#pragma unroll
    for (int mt = 0; mt < 2; mt++)
#pragma unroll
        for (int nt = 0; nt < 8; nt++)
#pragma unroll
            for (int e = 0; e < 4; e++) oacc[mt][nt][e] = 0.f;

    for (int kt = 0; kt < ntiles; kt++) {
        const int s = kt & 1;
        const int kbase = kt * 64;

        // store staged tile into slot s
#pragma unroll
        for (int i = 0; i < 4; i++) {
            *(uint4*)&Ksm[s * ASTG + lrow[i] * AR + lq[i]] = kst[i];
            *(uint4*)&Vsm[s * ASTG + lrow[i] * AR + lq[i]] = vst[i];
        }
        __syncthreads();

        // prefetch next tile into regs (overlaps with compute below)
        if (kt + 1 < ntiles) {
            const size_t base = (size_t)(kt + 1) * 64 * DK;
#pragma unroll
            for (int i = 0; i < 4; i++) {
                kst[i] = *(const uint4*)(Kg + base + (size_t)lrow[i] * DK + lq[i]);
                vst[i] = *(const uint4*)(Vg + base + (size_t)lrow[i] * DK + lq[i]);
            }
        }

        if (kbase <= q0 + lr0 + 31) {
            // ---- S = Q K^T  (32 x 64) ----
            float sacc[2][8][4];
#pragma unroll
            for (int mt = 0; mt < 2; mt++)
#pragma unroll
                for (int nt = 0; nt < 8; nt++)
#pragma unroll
                    for (int e = 0; e < 4; e++) sacc[mt][nt][e] = 0.f;

            const uint32_t* Ks_ = Ksm + s * ASTG;
#pragma unroll
            for (int kk = 0; kk < 8; kk++) {
                uint32_t aq[2][4];
#pragma unroll
                for (int mt = 0; mt < 2; mt++) {
                    const uint32_t* qp = Qsm + (lr0 + mt * 16 + g) * AR + kk * 8;
                    aq[mt][0] = qp[t];
                    aq[mt][1] = qp[8 * AR + t];
                    aq[mt][2] = qp[t + 4];
                    aq[mt][3] = qp[8 * AR + t + 4];
                }
#pragma unroll
                for (int nt = 0; nt < 8; nt++) {
                    const uint32_t* kp = Ks_ + (nt * 8 + g) * AR + kk * 8;
                    const uint32_t b0 = kp[t], b1 = kp[t + 4];
#pragma unroll
                    for (int mt = 0; mt < 2; mt++)
                        mma_tf32(sacc[mt][nt][0], sacc[mt][nt][1], sacc[mt][nt][2], sacc[mt][nt][3],
                                 aq[mt][0], aq[mt][1], aq[mt][2], aq[mt][3], b0, b1);
                }
            }

            // ---- causal mask (diagonal band only) ----
            if (kbase + 63 > q0 + lr0) {
#pragma unroll
                for (int mt = 0; mt < 2; mt++) {
                    const int rt_ = q0 + lr0 + mt * 16 + g;
                    const int rb_ = rt_ + 8;
#pragma unroll
                    for (int nt = 0; nt < 8; nt++) {
                        const int c0 = kbase + nt * 8 + 2 * t;
                        if (c0 > rt_)     sacc[mt][nt][0] = -1e30f;
                        if (c0 + 1 > rt_) sacc[mt][nt][1] = -1e30f;
                        if (c0 > rb_)     sacc[mt][nt][2] = -1e30f;
                        if (c0 + 1 > rb_) sacc[mt][nt][3] = -1e30f;
                    }
                }
            }

            // ---- online softmax (Q pre-scaled; base-2 exp) ----
#pragma unroll
            for (int mt = 0; mt < 2; mt++) {
                float mxt = -1e30f, mxb = -1e30f;
#pragma unroll
                for (int nt = 0; nt < 8; nt++) {
                    mxt = fmaxf(mxt, fmaxf(sacc[mt][nt][0], sacc[mt][nt][1]));
                    mxb = fmaxf(mxb, fmaxf(sacc[mt][nt][2], sacc[mt][nt][3]));
                }
                mxt = fmaxf(mxt, __shfl_xor_sync(0xffffffffu, mxt, 1));
                mxt = fmaxf(mxt, __shfl_xor_sync(0xffffffffu, mxt, 2));
                mxb = fmaxf(mxb, __shfl_xor_sync(0xffffffffu, mxb, 1));
                mxb = fmaxf(mxb, __shfl_xor_sync(0xffffffffu, mxb, 2));

                const int rc0 = mt * 2, rc1 = mt * 2 + 1;
                const float mnt = fmaxf(m_[rc0], mxt);
                const float mnb = fmaxf(m_[rc1], mxb);
                const float ct = ex2((m_[rc0] - mnt) * LOG2E);
                const float cb = ex2((m_[rc1] - mnb) * LOG2E);
                m_[rc0] = mnt; m_[rc1] = mnb;

                float st_ = 0.f, sb_ = 0.f;
                uint32_t* pr0 = Psm + (lr0 + mt * 16 + g) * AR;
                uint32_t* pr1 = pr0 + 8 * AR;
#pragma unroll
                for (int nt = 0; nt < 8; nt++) {
                    const float p0 = ex2((sacc[mt][nt][0] - mnt) * LOG2E);
                    const float p1 = ex2((sacc[mt][nt][1] - mnt) * LOG2E);
                    const float p2 = ex2((sacc[mt][nt][2] - mnb) * LOG2E);
                    const float p3 = ex2((sacc[mt][nt][3] - mnb) * LOG2E);
                    st_ += p0 + p1; sb_ += p2 + p3;
                    pr0[nt * 8 + 2 * t]     = f2tf32(p0);
                    pr0[nt * 8 + 2 * t + 1] = f2tf32(p1);
                    pr1[nt * 8 + 2 * t]     = f2tf32(p2);
                    pr1[nt * 8 + 2 * t + 1] = f2tf32(p3);
                }
                st_ += __shfl_xor_sync(0xffffffffu, st_, 1);
                st_ += __shfl_xor_sync(0xffffffffu, st_, 2);
                sb_ += __shfl_xor_sync(0xffffffffu, sb_, 1);
                sb_ += __shfl_xor_sync(0xffffffffu, sb_, 2);
                l_[rc0] = l_[rc0] * ct + st_;
                l_[rc1] = l_[rc1] * cb + sb_;
#pragma unroll
                for (int nt = 0; nt < 8; nt++) {
                    oacc[mt][nt][0] *= ct; oacc[mt][nt][1] *= ct;
                    oacc[mt][nt][2] *= cb; oacc[mt][nt][3] *= cb;
                }
            }
            __syncwarp();

            // ---- O += P V  (32 x 64 x 64) ----
            const uint32_t* Vs_ = Vsm + s * ASTG;
#pragma unroll
            for (int kk = 0; kk < 8; kk++) {
                uint32_t ap[2][4];
#pragma unroll
                for (int mt = 0; mt < 2; mt++) {
                    const uint32_t* pp = Psm + (lr0 + mt * 16 + g) * AR + kk * 8;
                    ap[mt][0] = pp[t];
                    ap[mt][1] = pp[8 * AR + t];
                    ap[mt][2] = pp[t + 4];
                    ap[mt][3] = pp[8 * AR + t + 4];
                }
                const uint32_t* vp0 = Vs_ + (kk * 8 + t) * AR;
                const uint32_t* vp1 = Vs_ + (kk * 8 + t + 4) * AR;
#pragma unroll
                for (int nt = 0; nt < 8; nt++) {
                    const uint32_t b0 = vp0[nt * 8 + g];
                    const uint32_t b1 = vp1[nt * 8 + g];
#pragma unroll
                    for (int mt = 0; mt < 2; mt++)
                        mma_tf32(oacc[mt][nt][0], oacc[mt][nt][1], oacc[mt][nt][2], oacc[mt][nt][3],
                                 ap[mt][0], ap[mt][1], ap[mt][2], ap[mt][3], b0, b1);
                }
            }
        }
        __syncthreads();   // slot s reads done before it is overwritten at kt+2
    }

    // ---- epilogue: O/l -> tf32 bits into g_Xr ----
    const int b_ = bh >> 4;
    const int h_ = bh & 15;
#pragma unroll
    for (int mt = 0; mt < 2; mt++) {
#pragma unroll
        for (int half = 0; half < 2; half++) {
            const int rc = mt * 2 + half;
            const float inv = 1.0f / l_[rc];
            const int row = q0 + lr0 + mt * 16 + g + 8 * half;
            uint32_t* dst = g_Xr + ((size_t)row * BBATCH + b_) * DDIM + h_ * DK;
#pragma unroll
            for (int nt = 0; nt < 8; nt++) {
                const int c = nt * 8 + 2 * t;
                uint2 o = make_uint2(f2tf32(oacc[mt][nt][half * 2 + 0] * inv),
                                     f2tf32(oacc[mt][nt][half * 2 + 1] * inv));
                *(uint2*)(dst + c) = o;
            }
        }
    }
}

// ---------------------------------------------------------------------------
// Launch
// ---------------------------------------------------------------------------
extern "C" void kernel_launch(void* const* d_in, const int* in_sizes, int n_in,
                              void* d_out, int out_size)
{
    (void)in_sizes; (void)n_in; (void)out_size;
    const float* query = (const float*)d_in[0];
    const float* key   = (const float*)d_in[1];
    const float* value = (const float*)d_in[2];
    const float* Wq = (const float*)d_in[4];
    const float* bq = (const float*)d_in[5];
    const float* Wk = (const float*)d_in[6];
    const float* bk = (const float*)d_in[7];
    const float* Wv = (const float*)d_in[8];
    const float* bv = (const float*)d_in[9];
    const float* Wo = (const float*)d_in[10];
    const float* bo = (const float*)d_in[11];
    float* out = (float*)d_out;

    cudaFuncSetAttribute(attn_tc, cudaFuncAttributeMaxDynamicSharedMemorySize, AT_SMEM);

    const int n4in = MM * DDIM / 4;      // 2,097,152
    const int n4w  = DDIM * DDIM / 4;    //   262,144
    cvt_tf32_kernel<<<n4in / 256, 256>>>(query, n4in, 0);
    cvt_tf32_kernel<<<n4in / 256, 256>>>(key,   n4in, 1);
    cvt_tf32_kernel<<<n4in / 256, 256>>>(value, n4in, 2);
    cvt_tf32_kernel<<<n4w / 256, 256>>>(Wq, n4w, 3);
    cvt_tf32_kernel<<<n4w / 256, 256>>>(Wk, n4w, 4);
    cvt_tf32_kernel<<<n4w / 256, 256>>>(Wv, n4w, 5);
    cvt_tf32_kernel<<<n4w / 256, 256>>>(Wo, n4w, 6);

    dim3 gGemm(DDIM / 128, MM / 128);    // (8, 64)
    gemm_tc<<<gGemm, 256>>>(bq, nullptr, 0);
    gemm_tc<<<gGemm, 256>>>(bk, nullptr, 1);
    gemm_tc<<<gGemm, 256>>>(bv, nullptr, 2);

    attn_tc<<<dim3(BBATCH * HH, SS / 256), 256, AT_SMEM>>>();

    gemm_tc<<<gGemm, 256>>>(bo, out, 3);
}